// round 16
// baseline (speedup 1.0000x reference)
#include <cuda_runtime.h>
#include <cuda_bf16.h>
#include <cstdint>

#define BB 4
#define CC 192
#define NN 8192
#define KK 16
#define COUT 192
#define TWOC 384

// Scratch
__device__ float          g_xt [(size_t)BB * NN * CC];   // x as [B, N, C] fp32
__device__ __nv_bfloat16  g_xhi[(size_t)BB * NN * CC];   // bf16 hi of x, [B, N, C]
__device__ __nv_bfloat16  g_xlo[(size_t)BB * NN * CC];   // bf16 lo
__device__ __nv_bfloat16  g_rhi[(size_t)BB * NN * CC];   // bf16 hi of rel, [B, N, C]
__device__ __nv_bfloat16  g_rlo[(size_t)BB * NN * CC];
__device__ __nv_bfloat16  g_whi[COUT * TWOC];
__device__ __nv_bfloat16  g_wlo[COUT * TWOC];

__device__ __forceinline__ uint32_t smem_u32(const void* p) {
    uint32_t a;
    asm("{ .reg .u64 t; cvta.to.shared.u64 t, %1; cvt.u32.u64 %0, t; }"
        : "=r"(a) : "l"(p));
    return a;
}

// ---------------------------------------------------------------------------
// Kernel 1: transpose x [B,C,N] -> g_xt fp32 [B,N,C] + bf16 hi/lo
// ---------------------------------------------------------------------------
__global__ void transpose_kernel(const float* __restrict__ x) {
    __shared__ float tile[32][33];
    int b  = blockIdx.z;
    int n0 = blockIdx.x * 32;
    int c0 = blockIdx.y * 32;
    int tx = threadIdx.x, ty = threadIdx.y;
    const float* in = x + (size_t)b * CC * NN;
#pragma unroll
    for (int i = 0; i < 32; i += 8)
        tile[ty + i][tx] = in[(size_t)(c0 + ty + i) * NN + n0 + tx];
    __syncthreads();
    float*         oxt = g_xt  + (size_t)b * NN * CC;
    __nv_bfloat16* ohi = g_xhi + (size_t)b * NN * CC;
    __nv_bfloat16* olo = g_xlo + (size_t)b * NN * CC;
#pragma unroll
    for (int i = 0; i < 32; i += 8) {
        float v = tile[tx][ty + i];
        size_t idx = (size_t)(n0 + ty + i) * CC + c0 + tx;
        oxt[idx] = v;
        __nv_bfloat16 h = __float2bfloat16(v);
        ohi[idx] = h;
        olo[idx] = __float2bfloat16(v - __bfloat162float(h));
    }
}

// ---------------------------------------------------------------------------
// Kernel 2: W -> Whi/Wlo bf16
// ---------------------------------------------------------------------------
__global__ void wsplit_kernel(const float* __restrict__ W) {
    int t = blockIdx.x * 256 + threadIdx.x;
    if (t < COUT * TWOC) {
        float v = W[t];
        __nv_bfloat16 h = __float2bfloat16(v);
        g_whi[t] = h;
        g_wlo[t] = __float2bfloat16(v - __bfloat162float(h));
    }
}

// ---------------------------------------------------------------------------
// Kernel 3: gather + max-relative -> relhi/rello bf16 [B,N,C]
// ---------------------------------------------------------------------------
#define GA_NODES 32

__device__ __forceinline__ void split_st2(float2 v, __nv_bfloat16* ph, __nv_bfloat16* pl) {
    __nv_bfloat16 hx = __float2bfloat16(v.x), hy = __float2bfloat16(v.y);
    __nv_bfloat162 h; h.x = hx; h.y = hy;
    __nv_bfloat162 l;
    l.x = __float2bfloat16(v.x - __bfloat162float(hx));
    l.y = __float2bfloat16(v.y - __bfloat162float(hy));
    *(__nv_bfloat162*)ph = h;
    *(__nv_bfloat162*)pl = l;
}

__global__ __launch_bounds__(256) void gather_kernel(const int* __restrict__ edge) {
    __shared__ int sj[GA_NODES * KK];
    __shared__ int si[GA_NODES * KK];

    const int tid = threadIdx.x;
    const int bid = blockIdx.x;
    const int b   = bid >> 8;
    const int n0  = (bid & 255) * GA_NODES;

    const int* ej = edge + ((size_t)b * NN + n0) * KK;
    const int* ei = edge + ((size_t)(BB + b) * NN + n0) * KK;
    for (int t = tid; t < GA_NODES * KK; t += 256) {
        sj[t] = ej[t];
        si[t] = ei[t];
    }
    __syncthreads();

    const float* bx = g_xt + (size_t)b * NN * CC;
    __nv_bfloat16* rhb = g_rhi + (size_t)(b * NN + n0) * CC;
    __nv_bfloat16* rlb = g_rlo + (size_t)(b * NN + n0) * CC;
    const int wid  = tid >> 5;
    const int lane = tid & 31;
    const int cb   = lane * 2;

#pragma unroll
    for (int t = 0; t < 2; t++) {
        const int nA = wid + t * 16;
        const int nB = nA + 8;
        float2 a0 = make_float2(-3.0e38f, -3.0e38f), a1 = a0, a2 = a0;
        float2 b0v = a0, b1 = a0, b2 = a0;
        const int* sjA = sj + nA * KK; const int* siA = si + nA * KK;
        const int* sjB = sj + nB * KK; const int* siB = si + nB * KK;
#pragma unroll 2
        for (int k = 0; k < KK; k++) {
            const float* pjA = bx + (size_t)sjA[k] * CC + cb;
            const float* piA = bx + (size_t)siA[k] * CC + cb;
            const float* pjB = bx + (size_t)sjB[k] * CC + cb;
            const float* piB = bx + (size_t)siB[k] * CC + cb;
            float2 ja0 = *(const float2*)(pjA);       float2 ia0 = *(const float2*)(piA);
            float2 ja1 = *(const float2*)(pjA + 64);  float2 ia1 = *(const float2*)(piA + 64);
            float2 ja2 = *(const float2*)(pjA + 128); float2 ia2 = *(const float2*)(piA + 128);
            float2 jb0 = *(const float2*)(pjB);       float2 ib0 = *(const float2*)(piB);
            float2 jb1 = *(const float2*)(pjB + 64);  float2 ib1 = *(const float2*)(piB + 64);
            float2 jb2 = *(const float2*)(pjB + 128); float2 ib2 = *(const float2*)(piB + 128);
            a0.x = fmaxf(a0.x, ja0.x - ia0.x); a0.y = fmaxf(a0.y, ja0.y - ia0.y);
            a1.x = fmaxf(a1.x, ja1.x - ia1.x); a1.y = fmaxf(a1.y, ja1.y - ia1.y);
            a2.x = fmaxf(a2.x, ja2.x - ia2.x); a2.y = fmaxf(a2.y, ja2.y - ia2.y);
            b0v.x = fmaxf(b0v.x, jb0.x - ib0.x); b0v.y = fmaxf(b0v.y, jb0.y - ib0.y);
            b1.x = fmaxf(b1.x, jb1.x - ib1.x); b1.y = fmaxf(b1.y, jb1.y - ib1.y);
            b2.x = fmaxf(b2.x, jb2.x - ib2.x); b2.y = fmaxf(b2.y, jb2.y - ib2.y);
        }
        split_st2(a0,  rhb + (size_t)nA * CC + cb,       rlb + (size_t)nA * CC + cb);
        split_st2(a1,  rhb + (size_t)nA * CC + cb + 64,  rlb + (size_t)nA * CC + cb + 64);
        split_st2(a2,  rhb + (size_t)nA * CC + cb + 128, rlb + (size_t)nA * CC + cb + 128);
        split_st2(b0v, rhb + (size_t)nB * CC + cb,       rlb + (size_t)nB * CC + cb);
        split_st2(b1,  rhb + (size_t)nB * CC + cb + 64,  rlb + (size_t)nB * CC + cb + 64);
        split_st2(b2,  rhb + (size_t)nB * CC + cb + 128, rlb + (size_t)nB * CC + cb + 128);
    }
}

// ---------------------------------------------------------------------------
// Kernel 4: merged HMMA GEMM, 128-node tile, 512 threads (16 warps), 1 CTA/SM.
// K=384 in 12 cp.async double-buffered chunks of 32.
// Warp (wm 0..3, wn 0..3): 32 nodes x 48 outs (same proven per-warp tile).
// ---------------------------------------------------------------------------
#define GT 512
#define ASTR 40    // smem row stride in bf16 (80B)

#define SA_H 0                    // 128 rows (A hi)
#define SA_L (128 * ASTR)         // 128 rows (A lo)
#define SB_H (256 * ASTR)         // 192 rows (W hi)
#define SB_L (448 * ASTR)         // 192 rows (W lo)
#define STAGE_ELEMS (640 * ASTR)
#define STAGE_BYTES (STAGE_ELEMS * 2)          // 51200
#define HM_SMEM (2 * STAGE_BYTES)              // 102400

__device__ __forceinline__ void cpa16(uint32_t s, const void* g) {
    asm volatile("cp.async.cg.shared.global [%0], [%1], 16;" :: "r"(s), "l"(g) : "memory");
}
#define CPA_COMMIT() asm volatile("cp.async.commit_group;" ::: "memory")
#define CPA_WAIT1()  asm volatile("cp.async.wait_group 1;" ::: "memory")
#define CPA_WAIT0()  asm volatile("cp.async.wait_group 0;" ::: "memory")

__device__ __forceinline__ void ldsm_x4(uint32_t a[4], uint32_t addr) {
    asm volatile("ldmatrix.sync.aligned.m8n8.x4.shared.b16 {%0,%1,%2,%3}, [%4];"
                 : "=r"(a[0]), "=r"(a[1]), "=r"(a[2]), "=r"(a[3]) : "r"(addr));
}
__device__ __forceinline__ void mma_bf16(float c[4], const uint32_t a[4],
                                         const uint32_t b[2]) {
    asm volatile(
        "mma.sync.aligned.m16n8k16.row.col.f32.bf16.bf16.f32 "
        "{%0,%1,%2,%3}, {%4,%5,%6,%7}, {%8,%9}, {%0,%1,%2,%3};"
        : "+f"(c[0]), "+f"(c[1]), "+f"(c[2]), "+f"(c[3])
        : "r"(a[0]), "r"(a[1]), "r"(a[2]), "r"(a[3]), "r"(b[0]), "r"(b[1]));
}

__global__ void __launch_bounds__(GT, 1)
gemm_hmma_kernel(const float* __restrict__ bias, float* __restrict__ out) {
    extern __shared__ char smem[];
    float* stg = (float*)smem;
    uint32_t sb = smem_u32(smem);

    const int tid  = threadIdx.x;
    const int lane = tid & 31;
    const int wid  = tid >> 5;
    const int wm   = wid & 3;                 // 4 x 32 nodes
    const int wn   = wid >> 2;                // 4 x 48 outs
    const int b    = blockIdx.x >> 6;
    const int n0   = (blockIdx.x & 63) * 128;

    const __nv_bfloat16* xh = g_xhi + (size_t)(b * NN + n0) * CC;
    const __nv_bfloat16* xl = g_xlo + (size_t)(b * NN + n0) * CC;
    const __nv_bfloat16* rh = g_rhi + (size_t)(b * NN + n0) * CC;
    const __nv_bfloat16* rl = g_rlo + (size_t)(b * NN + n0) * CC;

    const int arow = tid >> 2, aseg = tid & 3;   // A staging: 128 rows x 4 segs

    // stage loader: chunk c covers K cols [c*32, c*32+32); A source flips at c=6
    auto issue = [&](int c) {
        const uint32_t base = sb + (c & 1) * STAGE_BYTES;
        const int kc = c * 32;
        const __nv_bfloat16* Ah = (c < 6) ? xh : rh;
        const __nv_bfloat16* Al = (c < 6) ? xl : rl;
        const int ac = (c < 6) ? kc : kc - CC;
        cpa16(base + (SA_H + arow * ASTR + aseg * 8) * 2,
              Ah + (size_t)arow * CC + ac + aseg * 8);
        cpa16(base + (SA_L + arow * ASTR + aseg * 8) * 2,
              Al + (size_t)arow * CC + ac + aseg * 8);
        // W: 384 logical rows (0..191 hi, 192..383 lo) x 4 segs = 1536 / 512 = 3
#pragma unroll
        for (int it = 0; it < 3; it++) {
            int idx = it * GT + tid;
            int row = idx >> 2, seg = idx & 3;
            if (row < 192) {
                cpa16(base + (SB_H + row * ASTR + seg * 8) * 2,
                      g_whi + (size_t)row * TWOC + kc + seg * 8);
            } else {
                int r2 = row - 192;
                cpa16(base + (SB_L + r2 * ASTR + seg * 8) * 2,
                      g_wlo + (size_t)r2 * TWOC + kc + seg * 8);
            }
        }
        CPA_COMMIT();
    };

    float acc[2][6][4];
#pragma unroll
    for (int mt = 0; mt < 2; mt++)
#pragma unroll
        for (int nt = 0; nt < 6; nt++)
#pragma unroll
            for (int e = 0; e < 4; e++) acc[mt][nt][e] = 0.0f;

    issue(0);

    for (int c = 0; c < 12; c++) {
        if (c < 11) { issue(c + 1); CPA_WAIT1(); } else { CPA_WAIT0(); }
        __syncthreads();

        const uint32_t st = sb + (c & 1) * STAGE_BYTES;
#pragma unroll
        for (int ks = 0; ks < 32; ks += 16) {
            uint32_t ah[2][4], al[2][4];
#pragma unroll
            for (int mt = 0; mt < 2; mt++) {
                int m0 = wm * 32 + mt * 16;
                uint32_t off = ((m0 + (lane & 15)) * ASTR + ks + ((lane >> 4) << 3)) * 2;
                ldsm_x4(ah[mt], st + SA_H * 2 + off);
                ldsm_x4(al[mt], st + SA_L * 2 + off);
            }
            uint32_t bh[6][2], bl[6][2];
#pragma unroll
            for (int ntp = 0; ntp < 3; ntp++) {
                int o0 = wn * 48 + ntp * 16;
                uint32_t off = ((o0 + ((lane >> 4) << 3) + (lane & 7)) * ASTR
                               + ks + (((lane >> 3) & 1) << 3)) * 2;
                uint32_t r4[4];
                ldsm_x4(r4, st + SB_H * 2 + off);
                bh[2 * ntp][0] = r4[0]; bh[2 * ntp][1] = r4[1];
                bh[2 * ntp + 1][0] = r4[2]; bh[2 * ntp + 1][1] = r4[3];
                ldsm_x4(r4, st + SB_L * 2 + off);
                bl[2 * ntp][0] = r4[0]; bl[2 * ntp][1] = r4[1];
                bl[2 * ntp + 1][0] = r4[2]; bl[2 * ntp + 1][1] = r4[3];
            }
#pragma unroll
            for (int mt = 0; mt < 2; mt++)
#pragma unroll
                for (int nt = 0; nt < 6; nt++) {
                    mma_bf16(acc[mt][nt], ah[mt], bh[nt]);
                    mma_bf16(acc[mt][nt], ah[mt], bl[nt]);
                    mma_bf16(acc[mt][nt], al[mt], bh[nt]);
                }
        }
        __syncthreads();
    }

    // Epilogue: per out-quarter q (48 outs x 128 nodes), restage + coalesced
    // stores with bias + relu.
#define ESTR 129
    const int g   = lane >> 2;
    const int tig = lane & 3;
    for (int q = 0; q < 4; q++) {
        __syncthreads();
        if (wn == q) {
#pragma unroll
            for (int mt = 0; mt < 2; mt++)
#pragma unroll
                for (int nt = 0; nt < 6; nt++)
#pragma unroll
                    for (int e = 0; e < 4; e++) {
                        int m  = wm * 32 + mt * 16 + g + ((e >> 1) << 3);
                        int ol = nt * 8 + tig * 2 + (e & 1);
                        stg[ol * ESTR + m] = acc[mt][nt][e];
                    }
        }
        __syncthreads();
#pragma unroll
        for (int it = 0; it < 12; it++) {
            int idx = it * GT + tid;
            int r = idx >> 7, cn = idx & 127;
            int o = q * 48 + r;
            float v = stg[r * ESTR + cn] + bias[o];
            out[((size_t)b * COUT + o) * NN + n0 + cn] = fmaxf(v, 0.0f);
        }
    }
}

// ---------------------------------------------------------------------------
// Launch: single stream, sequential.
// ---------------------------------------------------------------------------
extern "C" void kernel_launch(void* const* d_in, const int* in_sizes, int n_in,
                              void* d_out, int out_size) {
    const float* x    = (const float*)d_in[0];
    const int*   edge = (const int*)d_in[2];
    const float* W    = (const float*)d_in[3];
    const float* bias = (const float*)d_in[4];
    float*       out  = (float*)d_out;

    static bool init = false;
    if (!init) {
        init = true;
        cudaFuncSetAttribute(gemm_hmma_kernel,
                             cudaFuncAttributeMaxDynamicSharedMemorySize, HM_SMEM);
    }

    wsplit_kernel<<<(COUT * TWOC + 255) / 256, 256>>>(W);
    transpose_kernel<<<dim3(NN / 32, CC / 32, BB), dim3(32, 8)>>>(x);
    gather_kernel<<<BB * (NN / GA_NODES), 256>>>(edge);
    gemm_hmma_kernel<<<BB * (NN / 128), GT, HM_SMEM>>>(bias, out);
}

// round 17
// speedup vs baseline: 1.0579x; 1.0579x over previous
#include <cuda_runtime.h>
#include <cuda_bf16.h>
#include <cstdint>

#define BB 4
#define CC 192
#define NN 8192
#define KK 16
#define COUT 192
#define TWOC 384

// Scratch
__device__ float          g_xt [(size_t)BB * NN * CC];   // x as [B, N, C] fp32
__device__ __nv_bfloat16  g_xhi[(size_t)BB * NN * CC];   // bf16 hi of x, [B, N, C]
__device__ __nv_bfloat16  g_xlo[(size_t)BB * NN * CC];   // bf16 lo
__device__ __nv_bfloat16  g_rhi[(size_t)BB * NN * CC];   // bf16 hi of rel, [B, N, C]
__device__ __nv_bfloat16  g_rlo[(size_t)BB * NN * CC];
__device__ __nv_bfloat16  g_whi[COUT * TWOC];
__device__ __nv_bfloat16  g_wlo[COUT * TWOC];

__device__ __forceinline__ uint32_t smem_u32(const void* p) {
    uint32_t a;
    asm("{ .reg .u64 t; cvta.to.shared.u64 t, %1; cvt.u32.u64 %0, t; }"
        : "=r"(a) : "l"(p));
    return a;
}

// ---------------------------------------------------------------------------
// Kernel 1: transpose x [B,C,N] -> g_xt fp32 [B,N,C] + bf16 hi/lo
// ---------------------------------------------------------------------------
__global__ void transpose_kernel(const float* __restrict__ x) {
    __shared__ float tile[32][33];
    int b  = blockIdx.z;
    int n0 = blockIdx.x * 32;
    int c0 = blockIdx.y * 32;
    int tx = threadIdx.x, ty = threadIdx.y;
    const float* in = x + (size_t)b * CC * NN;
#pragma unroll
    for (int i = 0; i < 32; i += 8)
        tile[ty + i][tx] = in[(size_t)(c0 + ty + i) * NN + n0 + tx];
    __syncthreads();
    float*         oxt = g_xt  + (size_t)b * NN * CC;
    __nv_bfloat16* ohi = g_xhi + (size_t)b * NN * CC;
    __nv_bfloat16* olo = g_xlo + (size_t)b * NN * CC;
#pragma unroll
    for (int i = 0; i < 32; i += 8) {
        float v = tile[tx][ty + i];
        size_t idx = (size_t)(n0 + ty + i) * CC + c0 + tx;
        oxt[idx] = v;
        __nv_bfloat16 h = __float2bfloat16(v);
        ohi[idx] = h;
        olo[idx] = __float2bfloat16(v - __bfloat162float(h));
    }
}

// ---------------------------------------------------------------------------
// Kernel 2: W -> Whi/Wlo bf16
// ---------------------------------------------------------------------------
__global__ void wsplit_kernel(const float* __restrict__ W) {
    int t = blockIdx.x * 256 + threadIdx.x;
    if (t < COUT * TWOC) {
        float v = W[t];
        __nv_bfloat16 h = __float2bfloat16(v);
        g_whi[t] = h;
        g_wlo[t] = __float2bfloat16(v - __bfloat162float(h));
    }
}

// ---------------------------------------------------------------------------
// Kernel 3: gather + max-relative -> relhi/rello bf16 [B,N,C]
// ---------------------------------------------------------------------------
#define GA_NODES 32

__device__ __forceinline__ void split_st2(float2 v, __nv_bfloat16* ph, __nv_bfloat16* pl) {
    __nv_bfloat16 hx = __float2bfloat16(v.x), hy = __float2bfloat16(v.y);
    __nv_bfloat162 h; h.x = hx; h.y = hy;
    __nv_bfloat162 l;
    l.x = __float2bfloat16(v.x - __bfloat162float(hx));
    l.y = __float2bfloat16(v.y - __bfloat162float(hy));
    *(__nv_bfloat162*)ph = h;
    *(__nv_bfloat162*)pl = l;
}

__global__ __launch_bounds__(256) void gather_kernel(const int* __restrict__ edge) {
    __shared__ int sj[GA_NODES * KK];
    __shared__ int si[GA_NODES * KK];

    const int tid = threadIdx.x;
    const int bid = blockIdx.x;
    const int b   = bid >> 8;
    const int n0  = (bid & 255) * GA_NODES;

    const int* ej = edge + ((size_t)b * NN + n0) * KK;
    const int* ei = edge + ((size_t)(BB + b) * NN + n0) * KK;
    for (int t = tid; t < GA_NODES * KK; t += 256) {
        sj[t] = ej[t];
        si[t] = ei[t];
    }
    __syncthreads();

    const float* bx = g_xt + (size_t)b * NN * CC;
    __nv_bfloat16* rhb = g_rhi + (size_t)(b * NN + n0) * CC;
    __nv_bfloat16* rlb = g_rlo + (size_t)(b * NN + n0) * CC;
    const int wid  = tid >> 5;
    const int lane = tid & 31;
    const int cb   = lane * 2;

#pragma unroll
    for (int t = 0; t < 2; t++) {
        const int nA = wid + t * 16;
        const int nB = nA + 8;
        float2 a0 = make_float2(-3.0e38f, -3.0e38f), a1 = a0, a2 = a0;
        float2 b0v = a0, b1 = a0, b2 = a0;
        const int* sjA = sj + nA * KK; const int* siA = si + nA * KK;
        const int* sjB = sj + nB * KK; const int* siB = si + nB * KK;
#pragma unroll 2
        for (int k = 0; k < KK; k++) {
            const float* pjA = bx + (size_t)sjA[k] * CC + cb;
            const float* piA = bx + (size_t)siA[k] * CC + cb;
            const float* pjB = bx + (size_t)sjB[k] * CC + cb;
            const float* piB = bx + (size_t)siB[k] * CC + cb;
            float2 ja0 = *(const float2*)(pjA);       float2 ia0 = *(const float2*)(piA);
            float2 ja1 = *(const float2*)(pjA + 64);  float2 ia1 = *(const float2*)(piA + 64);
            float2 ja2 = *(const float2*)(pjA + 128); float2 ia2 = *(const float2*)(piA + 128);
            float2 jb0 = *(const float2*)(pjB);       float2 ib0 = *(const float2*)(piB);
            float2 jb1 = *(const float2*)(pjB + 64);  float2 ib1 = *(const float2*)(piB + 64);
            float2 jb2 = *(const float2*)(pjB + 128); float2 ib2 = *(const float2*)(piB + 128);
            a0.x = fmaxf(a0.x, ja0.x - ia0.x); a0.y = fmaxf(a0.y, ja0.y - ia0.y);
            a1.x = fmaxf(a1.x, ja1.x - ia1.x); a1.y = fmaxf(a1.y, ja1.y - ia1.y);
            a2.x = fmaxf(a2.x, ja2.x - ia2.x); a2.y = fmaxf(a2.y, ja2.y - ia2.y);
            b0v.x = fmaxf(b0v.x, jb0.x - ib0.x); b0v.y = fmaxf(b0v.y, jb0.y - ib0.y);
            b1.x = fmaxf(b1.x, jb1.x - ib1.x); b1.y = fmaxf(b1.y, jb1.y - ib1.y);
            b2.x = fmaxf(b2.x, jb2.x - ib2.x); b2.y = fmaxf(b2.y, jb2.y - ib2.y);
        }
        split_st2(a0,  rhb + (size_t)nA * CC + cb,       rlb + (size_t)nA * CC + cb);
        split_st2(a1,  rhb + (size_t)nA * CC + cb + 64,  rlb + (size_t)nA * CC + cb + 64);
        split_st2(a2,  rhb + (size_t)nA * CC + cb + 128, rlb + (size_t)nA * CC + cb + 128);
        split_st2(b0v, rhb + (size_t)nB * CC + cb,       rlb + (size_t)nB * CC + cb);
        split_st2(b1,  rhb + (size_t)nB * CC + cb + 64,  rlb + (size_t)nB * CC + cb + 64);
        split_st2(b2,  rhb + (size_t)nB * CC + cb + 128, rlb + (size_t)nB * CC + cb + 128);
    }
}

// ---------------------------------------------------------------------------
// Kernel 4: merged HMMA GEMM, 128-node tile, 512 threads, 4-stage cp.async
// ring, ONE barrier per chunk (wait -> sync -> compute -> issue(c+3)).
// Warp (wm 0..3, wn 0..3): 32 nodes x 48 outs.
// ---------------------------------------------------------------------------
#define GT 512
#define ASTR 40    // smem row stride in bf16 (80B)

#define SA_H 0                    // 128 rows (A hi)
#define SA_L (128 * ASTR)         // 128 rows (A lo)
#define SB_H (256 * ASTR)         // 192 rows (W hi)
#define SB_L (448 * ASTR)         // 192 rows (W lo)
#define STAGE_ELEMS (640 * ASTR)
#define STAGE_BYTES (STAGE_ELEMS * 2)          // 51200
#define NSTAGE 4
#define HM_SMEM (NSTAGE * STAGE_BYTES)         // 204800

__device__ __forceinline__ void cpa16(uint32_t s, const void* g) {
    asm volatile("cp.async.cg.shared.global [%0], [%1], 16;" :: "r"(s), "l"(g) : "memory");
}
#define CPA_COMMIT() asm volatile("cp.async.commit_group;" ::: "memory")
#define CPA_WAIT2()  asm volatile("cp.async.wait_group 2;" ::: "memory")
#define CPA_WAIT1()  asm volatile("cp.async.wait_group 1;" ::: "memory")
#define CPA_WAIT0()  asm volatile("cp.async.wait_group 0;" ::: "memory")

__device__ __forceinline__ void ldsm_x4(uint32_t a[4], uint32_t addr) {
    asm volatile("ldmatrix.sync.aligned.m8n8.x4.shared.b16 {%0,%1,%2,%3}, [%4];"
                 : "=r"(a[0]), "=r"(a[1]), "=r"(a[2]), "=r"(a[3]) : "r"(addr));
}
__device__ __forceinline__ void mma_bf16(float c[4], const uint32_t a[4],
                                         const uint32_t b[2]) {
    asm volatile(
        "mma.sync.aligned.m16n8k16.row.col.f32.bf16.bf16.f32 "
        "{%0,%1,%2,%3}, {%4,%5,%6,%7}, {%8,%9}, {%0,%1,%2,%3};"
        : "+f"(c[0]), "+f"(c[1]), "+f"(c[2]), "+f"(c[3])
        : "r"(a[0]), "r"(a[1]), "r"(a[2]), "r"(a[3]), "r"(b[0]), "r"(b[1]));
}

__global__ void __launch_bounds__(GT, 1)
gemm_hmma_kernel(const float* __restrict__ bias, float* __restrict__ out) {
    extern __shared__ char smem[];
    float* stg = (float*)smem;
    uint32_t sb = smem_u32(smem);

    const int tid  = threadIdx.x;
    const int lane = tid & 31;
    const int wid  = tid >> 5;
    const int wm   = wid & 3;                 // 4 x 32 nodes
    const int wn   = wid >> 2;                // 4 x 48 outs
    const int b    = blockIdx.x >> 6;
    const int n0   = (blockIdx.x & 63) * 128;

    const __nv_bfloat16* xh = g_xhi + (size_t)(b * NN + n0) * CC;
    const __nv_bfloat16* xl = g_xlo + (size_t)(b * NN + n0) * CC;
    const __nv_bfloat16* rh = g_rhi + (size_t)(b * NN + n0) * CC;
    const __nv_bfloat16* rl = g_rlo + (size_t)(b * NN + n0) * CC;

    const int arow = tid >> 2, aseg = tid & 3;   // A staging: 128 rows x 4 segs

    // stage loader: chunk c covers K cols [c*32, c*32+32); A source flips at c=6
    auto issue = [&](int c) {
        const uint32_t base = sb + (c & (NSTAGE - 1)) * STAGE_BYTES;
        const int kc = c * 32;
        const __nv_bfloat16* Ah = (c < 6) ? xh : rh;
        const __nv_bfloat16* Al = (c < 6) ? xl : rl;
        const int ac = (c < 6) ? kc : kc - CC;
        cpa16(base + (SA_H + arow * ASTR + aseg * 8) * 2,
              Ah + (size_t)arow * CC + ac + aseg * 8);
        cpa16(base + (SA_L + arow * ASTR + aseg * 8) * 2,
              Al + (size_t)arow * CC + ac + aseg * 8);
#pragma unroll
        for (int it = 0; it < 3; it++) {
            int idx = it * GT + tid;
            int row = idx >> 2, seg = idx & 3;
            if (row < 192) {
                cpa16(base + (SB_H + row * ASTR + seg * 8) * 2,
                      g_whi + (size_t)row * TWOC + kc + seg * 8);
            } else {
                int r2 = row - 192;
                cpa16(base + (SB_L + r2 * ASTR + seg * 8) * 2,
                      g_wlo + (size_t)r2 * TWOC + kc + seg * 8);
            }
        }
        CPA_COMMIT();
    };

    float acc[2][6][4];
#pragma unroll
    for (int mt = 0; mt < 2; mt++)
#pragma unroll
        for (int nt = 0; nt < 6; nt++)
#pragma unroll
            for (int e = 0; e < 4; e++) acc[mt][nt][e] = 0.0f;

    issue(0);
    issue(1);
    issue(2);

    for (int c = 0; c < 12; c++) {
        // in-order group completion: <=min(11-c,2) pending => chunk c landed
        if (c <= 9)       CPA_WAIT2();
        else if (c == 10) CPA_WAIT1();
        else              CPA_WAIT0();
        __syncthreads();   // single barrier: data visible + buf (c-1)%4 free

        const uint32_t st = sb + (c & (NSTAGE - 1)) * STAGE_BYTES;
#pragma unroll
        for (int ks = 0; ks < 32; ks += 16) {
            uint32_t ah[2][4], al[2][4];
#pragma unroll
            for (int mt = 0; mt < 2; mt++) {
                int m0 = wm * 32 + mt * 16;
                uint32_t off = ((m0 + (lane & 15)) * ASTR + ks + ((lane >> 4) << 3)) * 2;
                ldsm_x4(ah[mt], st + SA_H * 2 + off);
                ldsm_x4(al[mt], st + SA_L * 2 + off);
            }
            uint32_t bh[6][2], bl[6][2];
#pragma unroll
            for (int ntp = 0; ntp < 3; ntp++) {
                int o0 = wn * 48 + ntp * 16;
                uint32_t off = ((o0 + ((lane >> 4) << 3) + (lane & 7)) * ASTR
                               + ks + (((lane >> 3) & 1) << 3)) * 2;
                uint32_t r4[4];
                ldsm_x4(r4, st + SB_H * 2 + off);
                bh[2 * ntp][0] = r4[0]; bh[2 * ntp][1] = r4[1];
                bh[2 * ntp + 1][0] = r4[2]; bh[2 * ntp + 1][1] = r4[3];
                ldsm_x4(r4, st + SB_L * 2 + off);
                bl[2 * ntp][0] = r4[0]; bl[2 * ntp][1] = r4[1];
                bl[2 * ntp + 1][0] = r4[2]; bl[2 * ntp + 1][1] = r4[3];
            }
#pragma unroll
            for (int mt = 0; mt < 2; mt++)
#pragma unroll
                for (int nt = 0; nt < 6; nt++) {
                    mma_bf16(acc[mt][nt], ah[mt], bh[nt]);
                    mma_bf16(acc[mt][nt], ah[mt], bl[nt]);
                    mma_bf16(acc[mt][nt], al[mt], bh[nt]);
                }
        }

        if (c <= 8) issue(c + 3);   // writes buf (c-1)%4 — freed by this barrier
    }
    __syncthreads();   // all compute done before epilogue reuses stage smem

    // Epilogue: per out-quarter q (48 outs x 128 nodes), restage + coalesced
    // stores with bias + relu.
#define ESTR 129
    const int g   = lane >> 2;
    const int tig = lane & 3;
    for (int q = 0; q < 4; q++) {
        if (q) __syncthreads();
        if (wn == q) {
#pragma unroll
            for (int mt = 0; mt < 2; mt++)
#pragma unroll
                for (int nt = 0; nt < 6; nt++)
#pragma unroll
                    for (int e = 0; e < 4; e++) {
                        int m  = wm * 32 + mt * 16 + g + ((e >> 1) << 3);
                        int ol = nt * 8 + tig * 2 + (e & 1);
                        stg[ol * ESTR + m] = acc[mt][nt][e];
                    }
        }
        __syncthreads();
#pragma unroll
        for (int it = 0; it < 12; it++) {
            int idx = it * GT + tid;
            int r = idx >> 7, cn = idx & 127;
            int o = q * 48 + r;
            float v = stg[r * ESTR + cn] + bias[o];
            out[((size_t)b * COUT + o) * NN + n0 + cn] = fmaxf(v, 0.0f);
        }
    }
}

// ---------------------------------------------------------------------------
// Launch: single stream, sequential.
// ---------------------------------------------------------------------------
extern "C" void kernel_launch(void* const* d_in, const int* in_sizes, int n_in,
                              void* d_out, int out_size) {
    const float* x    = (const float*)d_in[0];
    const int*   edge = (const int*)d_in[2];
    const float* W    = (const float*)d_in[3];
    const float* bias = (const float*)d_in[4];
    float*       out  = (float*)d_out;

    static bool init = false;
    if (!init) {
        init = true;
        cudaFuncSetAttribute(gemm_hmma_kernel,
                             cudaFuncAttributeMaxDynamicSharedMemorySize, HM_SMEM);
    }

    wsplit_kernel<<<(COUT * TWOC + 255) / 256, 256>>>(W);
    transpose_kernel<<<dim3(NN / 32, CC / 32, BB), dim3(32, 8)>>>(x);
    gather_kernel<<<BB * (NN / GA_NODES), 256>>>(edge);
    gemm_hmma_kernel<<<BB * (NN / 128), GT, HM_SMEM>>>(bias, out);
}